// round 2
// baseline (speedup 1.0000x reference)
#include <cuda_runtime.h>
#include <mma.h>
using namespace nvcuda;

// Problem dims
#define B_  8
#define L_  4096
#define D_  1024
#define N_  128
#define M_  (B_*L_)      // 32768 rows
#define LC  128          // scan chunk length
#define NC  (L_/LC)      // 32 chunks

// Scratch (static device globals — no runtime allocation)
__device__ float g_xproj[(size_t)M_ * N_];   // 16 MB: x_proj -> local h -> h_true
__device__ float g_carry[B_ * NC * N_];
__device__ float g_Hprev[B_ * NC * N_];
__device__ float g_lastu[B_ * N_];

__device__ __forceinline__ float to_tf32(float f) { return wmma::__float_to_tf32(f); }

// ---------------------------------------------------------------------------
// K1: x_proj[m,n] = sum_d x[m,d] * B_w[n,d]   (M=32768, K=1024, N=128)
// Block tile 128x128, BK=32, 8 warps (4x2), warp tile 32x64, tf32 wmma m16n16k8
// ---------------------------------------------------------------------------
__global__ __launch_bounds__(256) void k_gemm1(const float* __restrict__ x,
                                               const float* __restrict__ Bw)
{
    __shared__ float As[128][40];   // row-major m x k
    __shared__ float Bs[32][136];   // row-major k x n
    const int tid  = threadIdx.x;
    const int warp = tid >> 5;
    const int wm   = warp >> 1;     // 0..3
    const int wn   = warp & 1;      // 0..1
    const int m0   = blockIdx.x * 128;

    wmma::fragment<wmma::accumulator,16,16,8,float> acc[2][4];
    #pragma unroll
    for (int i = 0; i < 2; i++)
        #pragma unroll
        for (int j = 0; j < 4; j++)
            wmma::fill_fragment(acc[i][j], 0.0f);

    const float* Ag = x + (size_t)m0 * D_;

    for (int k0 = 0; k0 < D_; k0 += 32) {
        // A tile: 128 rows x 32 cols
        #pragma unroll
        for (int i = tid; i < 1024; i += 256) {
            int r  = i >> 3;
            int c4 = (i & 7) << 2;
            float4 v = *reinterpret_cast<const float4*>(Ag + (size_t)r * D_ + k0 + c4);
            As[r][c4+0] = to_tf32(v.x);
            As[r][c4+1] = to_tf32(v.y);
            As[r][c4+2] = to_tf32(v.z);
            As[r][c4+3] = to_tf32(v.w);
        }
        // B tile: Bs[k][n] = B_w[n*1024 + k0 + k]
        #pragma unroll
        for (int i = tid; i < 1024; i += 256) {
            int n  = i >> 3;
            int c4 = (i & 7) << 2;
            float4 v = *reinterpret_cast<const float4*>(Bw + (size_t)n * D_ + k0 + c4);
            Bs[c4+0][n] = to_tf32(v.x);
            Bs[c4+1][n] = to_tf32(v.y);
            Bs[c4+2][n] = to_tf32(v.z);
            Bs[c4+3][n] = to_tf32(v.w);
        }
        __syncthreads();

        #pragma unroll
        for (int kk = 0; kk < 4; kk++) {
            wmma::fragment<wmma::matrix_a,16,16,8,wmma::precision::tf32,wmma::row_major> af[2];
            wmma::fragment<wmma::matrix_b,16,16,8,wmma::precision::tf32,wmma::row_major> bf[4];
            #pragma unroll
            for (int i = 0; i < 2; i++)
                wmma::load_matrix_sync(af[i], &As[wm*32 + i*16][kk*8], 40);
            #pragma unroll
            for (int j = 0; j < 4; j++)
                wmma::load_matrix_sync(bf[j], &Bs[kk*8][wn*64 + j*16], 136);
            #pragma unroll
            for (int i = 0; i < 2; i++)
                #pragma unroll
                for (int j = 0; j < 4; j++)
                    wmma::mma_sync(acc[i][j], af[i], bf[j], acc[i][j]);
        }
        __syncthreads();
    }

    #pragma unroll
    for (int i = 0; i < 2; i++)
        #pragma unroll
        for (int j = 0; j < 4; j++)
            wmma::store_matrix_sync(g_xproj + (size_t)(m0 + wm*32 + i*16) * N_ + wn*64 + j*16,
                                    acc[i][j], N_, wmma::mem_row_major);
}

// ---------------------------------------------------------------------------
// K2: local scan per (b, chunk): overwrite g_xproj with local h (h0=0),
//     emit carry = h at chunk end, stash raw u at l=L-1.
// ---------------------------------------------------------------------------
__global__ __launch_bounds__(128) void k_scan(const float* __restrict__ logA)
{
    const int b = blockIdx.x >> 5;
    const int c = blockIdx.x & 31;
    const int n = threadIdx.x;
    const float a = expf(logA[n]);

    float* p = g_xproj + ((size_t)(b * L_ + c * LC)) * N_ + n;
    float h = 0.0f;
    float ulast = 0.0f;
    #pragma unroll 1
    for (int j = 0; j < LC; j += 4) {
        float u0 = p[0*N_], u1 = p[1*N_], u2 = p[2*N_], u3 = p[3*N_];
        h = fmaf(a, h, u0); p[0*N_] = h;
        h = fmaf(a, h, u1); p[1*N_] = h;
        h = fmaf(a, h, u2); p[2*N_] = h;
        h = fmaf(a, h, u3); p[3*N_] = h;
        ulast = u3;
        p += 4*N_;
    }
    g_carry[(size_t)(b * NC + c) * N_ + n] = h;
    if (c == NC - 1)
        g_lastu[b * N_ + n] = ulast;
}

// ---------------------------------------------------------------------------
// K3: carry exclusive scan across chunks (H_prev), + final_state output.
//     One block of 1024 threads = (b, n) pairs.
// ---------------------------------------------------------------------------
__global__ __launch_bounds__(1024) void k_carry(const float* __restrict__ logA,
                                                float* __restrict__ fs)
{
    const int t = threadIdx.x;
    const int b = t >> 7;
    const int n = t & 127;
    const float la  = logA[n];
    const float aLc = expf((float)LC * la);

    float H = 0.0f;
    #pragma unroll 1
    for (int c = 0; c < NC; c++) {
        size_t idx = (size_t)(b * NC + c) * N_ + n;
        g_Hprev[idx] = H;
        H = fmaf(aLc, H, g_carry[idx]);
    }

    if (b == 0) {
        float s = 0.0f;
        #pragma unroll
        for (int bb = 0; bb < B_; bb++) s += g_lastu[bb * N_ + n];
        s *= (1.0f / B_);
        #pragma unroll
        for (int bb = 0; bb < B_; bb++) fs[bb * N_ + n] = s;
    }
}

// ---------------------------------------------------------------------------
// K4: fixup: h_true[l] = local_h[l] + A^(j+1) * H_prev   (in place)
// ---------------------------------------------------------------------------
__global__ __launch_bounds__(128) void k_fix(const float* __restrict__ logA)
{
    const int b = blockIdx.x >> 5;
    const int c = blockIdx.x & 31;
    if (c == 0) return;
    const int n = threadIdx.x;
    const float a  = expf(logA[n]);
    const float Hp = g_Hprev[(size_t)(b * NC + c) * N_ + n];

    float f = a * Hp;
    float* p = g_xproj + ((size_t)(b * L_ + c * LC)) * N_ + n;
    #pragma unroll 4
    for (int j = 0; j < LC; j++) {
        p[0] += f;
        f *= a;
        p += N_;
    }
}

// ---------------------------------------------------------------------------
// K5: y[m,d] = sum_n h[m,n] * C_w[d,n] + x[m,d]*D_param[d]
//     (M=32768, K=128, N(out)=1024). Same tiling as K1, fused residual epilogue.
// ---------------------------------------------------------------------------
__global__ __launch_bounds__(256) void k_gemm2(const float* __restrict__ Cw,
                                               const float* __restrict__ x,
                                               const float* __restrict__ Dp,
                                               float* __restrict__ y)
{
    __shared__ float As[128][40];
    __shared__ float Bs[32][136];
    const int tid  = threadIdx.x;
    const int warp = tid >> 5;
    const int lane = tid & 31;
    const int wm   = warp >> 1;
    const int wn   = warp & 1;
    const int m0   = blockIdx.x * 128;
    const int d0   = blockIdx.y * 128;

    wmma::fragment<wmma::accumulator,16,16,8,float> acc[2][4];
    #pragma unroll
    for (int i = 0; i < 2; i++)
        #pragma unroll
        for (int j = 0; j < 4; j++)
            wmma::fill_fragment(acc[i][j], 0.0f);

    for (int k0 = 0; k0 < N_; k0 += 32) {
        // A tile from h (g_xproj), 128 x 32
        #pragma unroll
        for (int i = tid; i < 1024; i += 256) {
            int r  = i >> 3;
            int c4 = (i & 7) << 2;
            float4 v = *reinterpret_cast<const float4*>(g_xproj + (size_t)(m0 + r) * N_ + k0 + c4);
            As[r][c4+0] = to_tf32(v.x);
            As[r][c4+1] = to_tf32(v.y);
            As[r][c4+2] = to_tf32(v.z);
            As[r][c4+3] = to_tf32(v.w);
        }
        // B tile: Bs[k][d] = C_w[(d0+d)*128 + k0 + k]
        #pragma unroll
        for (int i = tid; i < 1024; i += 256) {
            int d  = i >> 3;
            int c4 = (i & 7) << 2;
            float4 v = *reinterpret_cast<const float4*>(Cw + (size_t)(d0 + d) * N_ + k0 + c4);
            Bs[c4+0][d] = to_tf32(v.x);
            Bs[c4+1][d] = to_tf32(v.y);
            Bs[c4+2][d] = to_tf32(v.z);
            Bs[c4+3][d] = to_tf32(v.w);
        }
        __syncthreads();

        #pragma unroll
        for (int kk = 0; kk < 4; kk++) {
            wmma::fragment<wmma::matrix_a,16,16,8,wmma::precision::tf32,wmma::row_major> af[2];
            wmma::fragment<wmma::matrix_b,16,16,8,wmma::precision::tf32,wmma::row_major> bf[4];
            #pragma unroll
            for (int i = 0; i < 2; i++)
                wmma::load_matrix_sync(af[i], &As[wm*32 + i*16][kk*8], 40);
            #pragma unroll
            for (int j = 0; j < 4; j++)
                wmma::load_matrix_sync(bf[j], &Bs[kk*8][wn*64 + j*16], 136);
            #pragma unroll
            for (int i = 0; i < 2; i++)
                #pragma unroll
                for (int j = 0; j < 4; j++)
                    wmma::mma_sync(acc[i][j], af[i], bf[j], acc[i][j]);
        }
        __syncthreads();
    }

    // Epilogue: per-warp frag staging in (reused) As, fused residual, write y.
    float* scb = &As[0][0] + warp * 384;   // 16 x 24 scratch per warp
    const int row  = lane >> 1;
    const int half = (lane & 1) << 3;

    #pragma unroll
    for (int i = 0; i < 2; i++) {
        #pragma unroll
        for (int j = 0; j < 4; j++) {
            wmma::store_matrix_sync(scb, acc[i][j], 24, wmma::mem_row_major);
            __syncwarp();
            const int mg = m0 + wm*32 + i*16 + row;
            const int dg = d0 + wn*64 + j*16 + half;
            float4 s0  = *reinterpret_cast<float4*>(scb + row*24 + half);
            float4 s1  = *reinterpret_cast<float4*>(scb + row*24 + half + 4);
            float4 xv0 = *reinterpret_cast<const float4*>(x + (size_t)mg * D_ + dg);
            float4 xv1 = *reinterpret_cast<const float4*>(x + (size_t)mg * D_ + dg + 4);
            float4 dv0 = *reinterpret_cast<const float4*>(Dp + dg);
            float4 dv1 = *reinterpret_cast<const float4*>(Dp + dg + 4);
            float4 o0, o1;
            o0.x = fmaf(xv0.x, dv0.x, s0.x);
            o0.y = fmaf(xv0.y, dv0.y, s0.y);
            o0.z = fmaf(xv0.z, dv0.z, s0.z);
            o0.w = fmaf(xv0.w, dv0.w, s0.w);
            o1.x = fmaf(xv1.x, dv1.x, s1.x);
            o1.y = fmaf(xv1.y, dv1.y, s1.y);
            o1.z = fmaf(xv1.z, dv1.z, s1.z);
            o1.w = fmaf(xv1.w, dv1.w, s1.w);
            *reinterpret_cast<float4*>(y + (size_t)mg * D_ + dg)     = o0;
            *reinterpret_cast<float4*>(y + (size_t)mg * D_ + dg + 4) = o1;
            __syncwarp();
        }
    }
}

// ---------------------------------------------------------------------------
extern "C" void kernel_launch(void* const* d_in, const int* in_sizes, int n_in,
                              void* d_out, int out_size)
{
    (void)in_sizes; (void)n_in; (void)out_size;
    const float* x    = (const float*)d_in[0];
    const float* Bw   = (const float*)d_in[1];
    const float* Cw   = (const float*)d_in[2];
    const float* logA = (const float*)d_in[3];
    const float* Dp   = (const float*)d_in[4];
    float* out = (float*)d_out;
    float* y_out = out;                         // (B, L, D)
    float* fs_out = out + (size_t)M_ * D_;      // (B, N)

    k_gemm1<<<M_/128, 256>>>(x, Bw);
    k_scan <<<B_*NC, 128>>>(logA);
    k_carry<<<1, 1024>>>(logA, fs_out);
    k_fix  <<<B_*NC, 128>>>(logA);
    dim3 g5(M_/128, D_/128);
    k_gemm2<<<g5, 256>>>(Cw, x, Dp, y_out);
}

// round 5
// speedup vs baseline: 1.5548x; 1.5548x over previous
#include <cuda_runtime.h>
#include <mma.h>
using namespace nvcuda;

// Problem dims
#define B_  8
#define L_  4096
#define D_  1024
#define N_  128
#define M_  (B_*L_)      // 32768 rows
#define LC  64           // scan chunk length
#define NC  (L_/LC)      // 64 chunks

// Scratch (static device globals — no runtime allocation)
__device__ float g_xproj[(size_t)M_ * N_];   // 16 MB: x_proj -> local h
__device__ float g_carry[B_ * NC * N_];
__device__ float g_Hprev[B_ * NC * N_];
__device__ float g_lastu[B_ * N_];
__device__ float g_powA[LC * N_];            // A[n]^(j+1), 32 KB, L2-resident

__device__ __forceinline__ float to_tf32(float f) { return wmma::__float_to_tf32(f); }

// ---------------------------------------------------------------------------
// K1: x_proj[m,n] = sum_d x[m,d] * B_w[n,d]   (M=32768, K=1024, N=128)
// Tile 128x128, BK=16, double-buffered smem, register-staged global loads,
// one barrier per K-step, 2 CTAs/SM.
// ---------------------------------------------------------------------------
__global__ __launch_bounds__(256, 2) void k_gemm1(const float* __restrict__ x,
                                                  const float* __restrict__ Bw)
{
    __shared__ float As[2][128][20];   // m x k, stride 20 (80B, 16B-aligned)
    __shared__ float Bs[2][16][132];   // k x n, stride 132 (528B, 16B-aligned)
    const int tid  = threadIdx.x;
    const int warp = tid >> 5;
    const int wm   = warp >> 1;     // 0..3
    const int wn   = warp & 1;      // 0..1
    const int m0   = blockIdx.x * 128;

    wmma::fragment<wmma::accumulator,16,16,8,float> acc[2][4];
    #pragma unroll
    for (int i = 0; i < 2; i++)
        #pragma unroll
        for (int j = 0; j < 4; j++)
            wmma::fill_fragment(acc[i][j], 0.0f);

    // Per-thread load map
    const int ar = tid >> 1;            // A row 0..127
    const int ac = (tid & 1) * 8;       // A col base 0 or 8
    const int bn = tid & 127;           // B n index
    const int bc = (tid >> 7) * 8;      // B k base 0 or 8

    const float* Axp = x + (size_t)(m0 + ar) * D_ + ac;
    const float* Bxp = Bw + (size_t)bn * D_ + bc;

    float4 a0, a1, b0, b1;

    auto loadG = [&](int k0) {
        a0 = *reinterpret_cast<const float4*>(Axp + k0);
        a1 = *reinterpret_cast<const float4*>(Axp + k0 + 4);
        b0 = *reinterpret_cast<const float4*>(Bxp + k0);
        b1 = *reinterpret_cast<const float4*>(Bxp + k0 + 4);
    };
    auto storeS = [&](int buf) {
        float4 c0 = make_float4(to_tf32(a0.x), to_tf32(a0.y), to_tf32(a0.z), to_tf32(a0.w));
        float4 c1 = make_float4(to_tf32(a1.x), to_tf32(a1.y), to_tf32(a1.z), to_tf32(a1.w));
        *reinterpret_cast<float4*>(&As[buf][ar][ac])     = c0;
        *reinterpret_cast<float4*>(&As[buf][ar][ac + 4]) = c1;
        Bs[buf][bc+0][bn] = to_tf32(b0.x);
        Bs[buf][bc+1][bn] = to_tf32(b0.y);
        Bs[buf][bc+2][bn] = to_tf32(b0.z);
        Bs[buf][bc+3][bn] = to_tf32(b0.w);
        Bs[buf][bc+4][bn] = to_tf32(b1.x);
        Bs[buf][bc+5][bn] = to_tf32(b1.y);
        Bs[buf][bc+6][bn] = to_tf32(b1.z);
        Bs[buf][bc+7][bn] = to_tf32(b1.w);
    };

    loadG(0);
    storeS(0);
    __syncthreads();

    int buf = 0;
    for (int k0 = 0; k0 < D_; k0 += 16) {
        const int nxt = k0 + 16;
        if (nxt < D_) loadG(nxt);

        #pragma unroll
        for (int kk = 0; kk < 2; kk++) {
            wmma::fragment<wmma::matrix_a,16,16,8,wmma::precision::tf32,wmma::row_major> af[2];
            wmma::fragment<wmma::matrix_b,16,16,8,wmma::precision::tf32,wmma::row_major> bf[4];
            #pragma unroll
            for (int i = 0; i < 2; i++)
                wmma::load_matrix_sync(af[i], &As[buf][wm*32 + i*16][kk*8], 20);
            #pragma unroll
            for (int j = 0; j < 4; j++)
                wmma::load_matrix_sync(bf[j], &Bs[buf][kk*8][wn*64 + j*16], 132);
            #pragma unroll
            for (int i = 0; i < 2; i++)
                #pragma unroll
                for (int j = 0; j < 4; j++)
                    wmma::mma_sync(acc[i][j], af[i], bf[j], acc[i][j]);
        }

        if (nxt < D_) storeS(buf ^ 1);
        __syncthreads();
        buf ^= 1;
    }

    #pragma unroll
    for (int i = 0; i < 2; i++)
        #pragma unroll
        for (int j = 0; j < 4; j++)
            wmma::store_matrix_sync(g_xproj + (size_t)(m0 + wm*32 + i*16) * N_ + wn*64 + j*16,
                                    acc[i][j], N_, wmma::mem_row_major);
}

// ---------------------------------------------------------------------------
// K2: local scan per (b, chunk): overwrite g_xproj with local h (h0=0),
//     emit carry = h at chunk end, stash raw u at l=L-1.
// ---------------------------------------------------------------------------
__global__ __launch_bounds__(128) void k_scan(const float* __restrict__ logA)
{
    const int b = blockIdx.x >> 6;      // NC=64
    const int c = blockIdx.x & 63;
    const int n = threadIdx.x;
    const float a = expf(logA[n]);

    float* p = g_xproj + ((size_t)(b * L_ + c * LC)) * N_ + n;
    float h = 0.0f;
    float ulast = 0.0f;
    #pragma unroll 1
    for (int j = 0; j < LC; j += 4) {
        float u0 = p[0*N_], u1 = p[1*N_], u2 = p[2*N_], u3 = p[3*N_];
        h = fmaf(a, h, u0); p[0*N_] = h;
        h = fmaf(a, h, u1); p[1*N_] = h;
        h = fmaf(a, h, u2); p[2*N_] = h;
        h = fmaf(a, h, u3); p[3*N_] = h;
        ulast = u3;
        p += 4*N_;
    }
    g_carry[(size_t)(b * NC + c) * N_ + n] = h;
    if (c == NC - 1)
        g_lastu[b * N_ + n] = ulast;
}

// ---------------------------------------------------------------------------
// K3: carry exclusive scan across chunks (H_prev), + final_state output.
//     One block of 1024 threads = (b, n) pairs.
// ---------------------------------------------------------------------------
__global__ __launch_bounds__(1024) void k_carry(const float* __restrict__ logA,
                                                float* __restrict__ fs)
{
    const int t = threadIdx.x;
    const int b = t >> 7;
    const int n = t & 127;
    const float la  = logA[n];
    const float aLc = expf((float)LC * la);

    float H = 0.0f;
    #pragma unroll 1
    for (int c = 0; c < NC; c++) {
        size_t idx = (size_t)(b * NC + c) * N_ + n;
        g_Hprev[idx] = H;
        H = fmaf(aLc, H, g_carry[idx]);
    }

    if (b == 0) {
        float s = 0.0f;
        #pragma unroll
        for (int bb = 0; bb < B_; bb++) s += g_lastu[bb * N_ + n];
        s *= (1.0f / B_);
        #pragma unroll
        for (int bb = 0; bb < B_; bb++) fs[bb * N_ + n] = s;
    }
}

// ---------------------------------------------------------------------------
// K3b: powA table: g_powA[j][n] = A[n]^(j+1)
// ---------------------------------------------------------------------------
__global__ __launch_bounds__(1024) void k_pow(const float* __restrict__ logA)
{
    const int idx = blockIdx.x * 1024 + threadIdx.x;   // LC*N_ = 8192 elems
    const int j = idx >> 7;
    const int n = idx & 127;
    g_powA[idx] = expf(logA[n] * (float)(j + 1));
}

// ---------------------------------------------------------------------------
// K5: y[m,d] = sum_n h_true[m,n] * C_w[d,n] + x[m,d]*D_param[d]
// where h_true is reconstructed on the fly during the A-tile load:
//   h_true[l0+j, n] = local_h[l0+j, n] + A[n]^(j+1) * H_prev[b, c, n]
// Tile 128x128, BK=16, double-buffered, d-tiles are the fast grid dim
// so concurrent blocks share A-tiles in L2.
// ---------------------------------------------------------------------------
__global__ __launch_bounds__(256, 2) void k_gemm2(const float* __restrict__ Cw,
                                                  const float* __restrict__ x,
                                                  const float* __restrict__ Dp,
                                                  float* __restrict__ y)
{
    __shared__ float As[2][128][20];
    __shared__ float Bs[2][16][132];
    const int tid  = threadIdx.x;
    const int warp = tid >> 5;
    const int lane = tid & 31;
    const int wm   = warp >> 1;
    const int wn   = warp & 1;
    const int d0   = blockIdx.x * 128;   // fast dim: 8 d-tiles
    const int m0   = blockIdx.y * 128;   // slow dim: 256 m-tiles

    const int b_idx = m0 >> 12;                 // m0 / 4096
    const int c0    = (m0 & (L_ - 1)) >> 6;     // first chunk in this m-tile

    wmma::fragment<wmma::accumulator,16,16,8,float> acc[2][4];
    #pragma unroll
    for (int i = 0; i < 2; i++)
        #pragma unroll
        for (int j = 0; j < 4; j++)
            wmma::fill_fragment(acc[i][j], 0.0f);

    // Per-thread load map
    const int ar = tid >> 1;            // A row 0..127 (= local l within 2 chunks)
    const int ac = (tid & 1) * 8;       // A col base (n dim)
    const int bd = tid & 127;           // B d index
    const int bc = (tid >> 7) * 8;      // B k base

    const float* Axp = g_xproj + (size_t)(m0 + ar) * N_ + ac;
    const float* Pwp = g_powA + (size_t)(ar & (LC-1)) * N_ + ac;
    const float* Hpp = g_Hprev + (size_t)(b_idx * NC + c0 + (ar >> 6)) * N_ + ac;
    const float* Bxp = Cw + (size_t)(d0 + bd) * N_ + bc;

    float4 a0, a1, b0, b1;

    auto loadG = [&](int k0) {
        float4 xp0 = *reinterpret_cast<const float4*>(Axp + k0);
        float4 xp1 = *reinterpret_cast<const float4*>(Axp + k0 + 4);
        float4 pw0 = *reinterpret_cast<const float4*>(Pwp + k0);
        float4 pw1 = *reinterpret_cast<const float4*>(Pwp + k0 + 4);
        float4 hp0 = *reinterpret_cast<const float4*>(Hpp + k0);
        float4 hp1 = *reinterpret_cast<const float4*>(Hpp + k0 + 4);
        a0.x = fmaf(pw0.x, hp0.x, xp0.x);
        a0.y = fmaf(pw0.y, hp0.y, xp0.y);
        a0.z = fmaf(pw0.z, hp0.z, xp0.z);
        a0.w = fmaf(pw0.w, hp0.w, xp0.w);
        a1.x = fmaf(pw1.x, hp1.x, xp1.x);
        a1.y = fmaf(pw1.y, hp1.y, xp1.y);
        a1.z = fmaf(pw1.z, hp1.z, xp1.z);
        a1.w = fmaf(pw1.w, hp1.w, xp1.w);
        b0 = *reinterpret_cast<const float4*>(Bxp + k0);
        b1 = *reinterpret_cast<const float4*>(Bxp + k0 + 4);
    };
    auto storeS = [&](int buf) {
        float4 c0v = make_float4(to_tf32(a0.x), to_tf32(a0.y), to_tf32(a0.z), to_tf32(a0.w));
        float4 c1v = make_float4(to_tf32(a1.x), to_tf32(a1.y), to_tf32(a1.z), to_tf32(a1.w));
        *reinterpret_cast<float4*>(&As[buf][ar][ac])     = c0v;
        *reinterpret_cast<float4*>(&As[buf][ar][ac + 4]) = c1v;
        Bs[buf][bc+0][bd] = to_tf32(b0.x);
        Bs[buf][bc+1][bd] = to_tf32(b0.y);
        Bs[buf][bc+2][bd] = to_tf32(b0.z);
        Bs[buf][bc+3][bd] = to_tf32(b0.w);
        Bs[buf][bc+4][bd] = to_tf32(b1.x);
        Bs[buf][bc+5][bd] = to_tf32(b1.y);
        Bs[buf][bc+6][bd] = to_tf32(b1.z);
        Bs[buf][bc+7][bd] = to_tf32(b1.w);
    };

    loadG(0);
    storeS(0);
    __syncthreads();

    int buf = 0;
    for (int k0 = 0; k0 < N_; k0 += 16) {
        const int nxt = k0 + 16;
        if (nxt < N_) loadG(nxt);

        #pragma unroll
        for (int kk = 0; kk < 2; kk++) {
            wmma::fragment<wmma::matrix_a,16,16,8,wmma::precision::tf32,wmma::row_major> af[2];
            wmma::fragment<wmma::matrix_b,16,16,8,wmma::precision::tf32,wmma::row_major> bf[4];
            #pragma unroll
            for (int i = 0; i < 2; i++)
                wmma::load_matrix_sync(af[i], &As[buf][wm*32 + i*16][kk*8], 20);
            #pragma unroll
            for (int j = 0; j < 4; j++)
                wmma::load_matrix_sync(bf[j], &Bs[buf][kk*8][wn*64 + j*16], 132);
            #pragma unroll
            for (int i = 0; i < 2; i++)
                #pragma unroll
                for (int j = 0; j < 4; j++)
                    wmma::mma_sync(acc[i][j], af[i], bf[j], acc[i][j]);
        }

        if (nxt < N_) storeS(buf ^ 1);
        __syncthreads();
        buf ^= 1;
    }

    // Epilogue: per-warp frag staging in (reused) As, fused residual, write y.
    float* scb = &As[0][0][0] + warp * 384;   // 16 x 24 scratch per warp
    const int row  = lane >> 1;
    const int half = (lane & 1) << 3;

    #pragma unroll
    for (int i = 0; i < 2; i++) {
        #pragma unroll
        for (int j = 0; j < 4; j++) {
            wmma::store_matrix_sync(scb, acc[i][j], 24, wmma::mem_row_major);
            __syncwarp();
            const int mg = m0 + wm*32 + i*16 + row;
            const int dg = d0 + wn*64 + j*16 + half;
            float4 s0  = *reinterpret_cast<float4*>(scb + row*24 + half);
            float4 s1  = *reinterpret_cast<float4*>(scb + row*24 + half + 4);
            float4 xv0 = *reinterpret_cast<const float4*>(x + (size_t)mg * D_ + dg);
            float4 xv1 = *reinterpret_cast<const float4*>(x + (size_t)mg * D_ + dg + 4);
            float4 dv0 = *reinterpret_cast<const float4*>(Dp + dg);
            float4 dv1 = *reinterpret_cast<const float4*>(Dp + dg + 4);
            float4 o0, o1;
            o0.x = fmaf(xv0.x, dv0.x, s0.x);
            o0.y = fmaf(xv0.y, dv0.y, s0.y);
            o0.z = fmaf(xv0.z, dv0.z, s0.z);
            o0.w = fmaf(xv0.w, dv0.w, s0.w);
            o1.x = fmaf(xv1.x, dv1.x, s1.x);
            o1.y = fmaf(xv1.y, dv1.y, s1.y);
            o1.z = fmaf(xv1.z, dv1.z, s1.z);
            o1.w = fmaf(xv1.w, dv1.w, s1.w);
            *reinterpret_cast<float4*>(y + (size_t)mg * D_ + dg)     = o0;
            *reinterpret_cast<float4*>(y + (size_t)mg * D_ + dg + 4) = o1;
            __syncwarp();
        }
    }
}

// ---------------------------------------------------------------------------
extern "C" void kernel_launch(void* const* d_in, const int* in_sizes, int n_in,
                              void* d_out, int out_size)
{
    (void)in_sizes; (void)n_in; (void)out_size;
    const float* x    = (const float*)d_in[0];
    const float* Bw   = (const float*)d_in[1];
    const float* Cw   = (const float*)d_in[2];
    const float* logA = (const float*)d_in[3];
    const float* Dp   = (const float*)d_in[4];
    float* out = (float*)d_out;
    float* y_out = out;                         // (B, L, D)
    float* fs_out = out + (size_t)M_ * D_;      // (B, N)

    k_pow  <<<(LC*N_)/1024, 1024>>>(logA);
    k_gemm1<<<M_/128, 256>>>(x, Bw);
    k_scan <<<B_*NC, 128>>>(logA);
    k_carry<<<1, 1024>>>(logA, fs_out);
    dim3 g5(D_/128, M_/128);
    k_gemm2<<<g5, 256>>>(Cw, x, Dp, y_out);
}

// round 12
// speedup vs baseline: 2.1281x; 1.3687x over previous
#include <cuda_runtime.h>
#include <cstdint>

// Problem dims
#define B_  8
#define L_  4096
#define D_  1024
#define N_  128
#define M_  (B_*L_)      // 32768 rows
#define LC  64           // scan chunk length
#define NC  (L_/LC)      // 64 chunks

// Scratch (static device globals — no runtime allocation)
__device__ float g_xproj[(size_t)M_ * N_];   // 16 MB: x_proj -> local h
__device__ float g_carry[B_ * NC * N_];
__device__ float g_Hprev[B_ * NC * N_];
__device__ float g_lastu[B_ * N_];
__device__ float g_powA[LC * N_];            // A[n]^(j+1)
__device__ float g_BwR[N_ * D_];             // RN-tf32-rounded B_w
__device__ float g_CwR[D_ * N_];             // RN-tf32-rounded C_w

__device__ __forceinline__ float to_tf32(float f) {
    float r; asm("cvt.rna.tf32.f32 %0, %1;" : "=f"(r) : "f"(f)); return r;
}

// ---------------------------------------------------------------------------
// mma.sync tf32 GEMM:  out[m, n] = sum_k A[m, k] * Brows[n, k]
//   Block tile 128(M) x 128(N), BK = 16, double-buffered smem, register-
//   staged global loads (RN-tf32 rounding applied on the A path), one
//   barrier per K-step.  8 warps in 2x4: warp tile 64(M) x 32(N),
//   fragments m16n8k8, 4x4 accumulator grid per warp.
//   Smem stride 20 floats: bank = (20r + c) % 32 is a bijection over the
//   fragment access pattern (r = lane/4 in 0..7, c = lane%4 in 0..7) ->
//   conflict-free LDS.
//   RESID: A = g_xproj with fused h_true reconstruction
//          (h_true = local_h + A^(j+1) * H_prev), epilogue adds x * Dp.
// ---------------------------------------------------------------------------
template<int KTOT, bool RESID>
__global__ __launch_bounds__(256, 2) void k_gemm(
    const float* __restrict__ Aptr, int ldA,
    const float* __restrict__ Bptr, int ldB,
    const float* __restrict__ xres,
    const float* __restrict__ Dp,
    float* __restrict__ outp)
{
    __shared__ float As[2][128][20];
    __shared__ float Bs[2][128][20];   // n-major: Bs[n][k]
    const int tid  = threadIdx.x;
    const int warp = tid >> 5;
    const int lane = tid & 31;
    const int wm   = warp >> 2;        // 0..1 -> m offset wm*64
    const int wn   = warp & 3;         // 0..3 -> n offset wn*32
    const int grp  = lane >> 2;        // 0..7
    const int thr  = lane & 3;         // 0..3
    const int d0   = RESID ? blockIdx.x * 128 : 0;
    const int m0   = RESID ? blockIdx.y * 128 : blockIdx.x * 128;

    float d[4][4][4];
    #pragma unroll
    for (int mf = 0; mf < 4; mf++)
        #pragma unroll
        for (int nf = 0; nf < 4; nf++)
            #pragma unroll
            for (int q = 0; q < 4; q++) d[mf][nf][q] = 0.0f;

    // Loader map: A tile 128 x 16 (row = tid>>1, 8 cols at (tid&1)*8)
    const int ar = tid >> 1;
    const int ac = (tid & 1) * 8;
    const int br = tid & 127;
    const int bc = (tid >> 7) * 8;

    const float* Ag = Aptr + (size_t)(m0 + ar) * ldA + ac;
    const float* Bg = Bptr + (size_t)(d0 + br) * ldB + bc;

    const float* Pw = nullptr;
    const float* Hp = nullptr;
    if (RESID) {
        const int b_idx = m0 >> 12;              // m0 / 4096
        const int c0    = (m0 & (L_ - 1)) >> 6;  // first chunk in tile
        Pw = g_powA  + (size_t)(ar & (LC - 1)) * N_ + ac;
        Hp = g_Hprev + (size_t)(b_idx * NC + c0 + (ar >> 6)) * N_ + ac;
    }

    float4 a0v, a1v, b0v, b1v;

    auto loadG = [&](int k0) {
        float4 x0 = *reinterpret_cast<const float4*>(Ag + k0);
        float4 x1 = *reinterpret_cast<const float4*>(Ag + k0 + 4);
        if (RESID) {
            float4 p0 = *reinterpret_cast<const float4*>(Pw + k0);
            float4 p1 = *reinterpret_cast<const float4*>(Pw + k0 + 4);
            float4 h0 = *reinterpret_cast<const float4*>(Hp + k0);
            float4 h1 = *reinterpret_cast<const float4*>(Hp + k0 + 4);
            x0.x = fmaf(p0.x, h0.x, x0.x); x0.y = fmaf(p0.y, h0.y, x0.y);
            x0.z = fmaf(p0.z, h0.z, x0.z); x0.w = fmaf(p0.w, h0.w, x0.w);
            x1.x = fmaf(p1.x, h1.x, x1.x); x1.y = fmaf(p1.y, h1.y, x1.y);
            x1.z = fmaf(p1.z, h1.z, x1.z); x1.w = fmaf(p1.w, h1.w, x1.w);
        }
        a0v = x0; a1v = x1;
        b0v = *reinterpret_cast<const float4*>(Bg + k0);
        b1v = *reinterpret_cast<const float4*>(Bg + k0 + 4);
    };
    auto storeS = [&](int s) {
        // A path: RN-round to tf32.  B path: weights pre-rounded in k_prep.
        float4 c0 = make_float4(to_tf32(a0v.x), to_tf32(a0v.y), to_tf32(a0v.z), to_tf32(a0v.w));
        float4 c1 = make_float4(to_tf32(a1v.x), to_tf32(a1v.y), to_tf32(a1v.z), to_tf32(a1v.w));
        *reinterpret_cast<float4*>(&As[s][ar][ac])     = c0;
        *reinterpret_cast<float4*>(&As[s][ar][ac + 4]) = c1;
        *reinterpret_cast<float4*>(&Bs[s][br][bc])     = b0v;
        *reinterpret_cast<float4*>(&Bs[s][br][bc + 4]) = b1v;
    };

    loadG(0);
    storeS(0);
    __syncthreads();

    int buf = 0;
    for (int k0 = 0; k0 < KTOT; k0 += 16) {
        const int nxt = k0 + 16;
        if (nxt < KTOT) loadG(nxt);

        #pragma unroll
        for (int ks = 0; ks < 2; ks++) {
            uint32_t a[4][4], b[4][2];
            #pragma unroll
            for (int mf = 0; mf < 4; mf++) {
                const float* ap = &As[buf][wm*64 + mf*16][ks*8];
                a[mf][0] = __float_as_uint(ap[ grp      * 20 + thr    ]);
                a[mf][1] = __float_as_uint(ap[(grp + 8) * 20 + thr    ]);
                a[mf][2] = __float_as_uint(ap[ grp      * 20 + thr + 4]);
                a[mf][3] = __float_as_uint(ap[(grp + 8) * 20 + thr + 4]);
            }
            #pragma unroll
            for (int nf = 0; nf < 4; nf++) {
                const float* bp = &Bs[buf][wn*32 + nf*8][ks*8];
                b[nf][0] = __float_as_uint(bp[grp * 20 + thr    ]);
                b[nf][1] = __float_as_uint(bp[grp * 20 + thr + 4]);
            }
            #pragma unroll
            for (int mf = 0; mf < 4; mf++)
                #pragma unroll
                for (int nf = 0; nf < 4; nf++)
                    asm volatile(
                        "mma.sync.aligned.m16n8k8.row.col.f32.tf32.tf32.f32 "
                        "{%0,%1,%2,%3}, {%4,%5,%6,%7}, {%8,%9}, {%0,%1,%2,%3};"
                        : "+f"(d[mf][nf][0]), "+f"(d[mf][nf][1]),
                          "+f"(d[mf][nf][2]), "+f"(d[mf][nf][3])
                        : "r"(a[mf][0]), "r"(a[mf][1]), "r"(a[mf][2]), "r"(a[mf][3]),
                          "r"(b[nf][0]), "r"(b[nf][1]));
        }

        if (nxt < KTOT) storeS(buf ^ 1);
        __syncthreads();
        buf ^= 1;
    }

    // Epilogue: direct stores.  c0/c1 at (row, 2*thr .. +1), c2/c3 at row+8.
    #pragma unroll
    for (int mf = 0; mf < 4; mf++) {
        const int mg = m0 + wm*64 + mf*16 + grp;
        #pragma unroll
        for (int nf = 0; nf < 4; nf++) {
            const int cg = wn*32 + nf*8 + 2*thr;
            if (!RESID) {
                *reinterpret_cast<float2*>(outp + (size_t)mg * N_ + cg) =
                    make_float2(d[mf][nf][0], d[mf][nf][1]);
                *reinterpret_cast<float2*>(outp + (size_t)(mg + 8) * N_ + cg) =
                    make_float2(d[mf][nf][2], d[mf][nf][3]);
            } else {
                const int dg = d0 + cg;
                float2 dv  = *reinterpret_cast<const float2*>(Dp + dg);
                float2 xv0 = *reinterpret_cast<const float2*>(xres + (size_t)mg * D_ + dg);
                float2 xv1 = *reinterpret_cast<const float2*>(xres + (size_t)(mg + 8) * D_ + dg);
                *reinterpret_cast<float2*>(outp + (size_t)mg * D_ + dg) =
                    make_float2(fmaf(xv0.x, dv.x, d[mf][nf][0]),
                                fmaf(xv0.y, dv.y, d[mf][nf][1]));
                *reinterpret_cast<float2*>(outp + (size_t)(mg + 8) * D_ + dg) =
                    make_float2(fmaf(xv1.x, dv.x, d[mf][nf][2]),
                                fmaf(xv1.y, dv.y, d[mf][nf][3]));
            }
        }
    }
}

// ---------------------------------------------------------------------------
// Prep: RN-round weights to tf32
// ---------------------------------------------------------------------------
__global__ __launch_bounds__(256) void k_prep(const float* __restrict__ Bw,
                                              const float* __restrict__ Cw)
{
    const int i = blockIdx.x * 256 + threadIdx.x;   // 131072 each
    g_BwR[i] = to_tf32(Bw[i]);
    g_CwR[i] = to_tf32(Cw[i]);
}

// powA table: g_powA[j][n] = A[n]^(j+1)
__global__ __launch_bounds__(1024) void k_pow(const float* __restrict__ logA)
{
    const int idx = blockIdx.x * 1024 + threadIdx.x;   // LC*N_ = 8192
    const int j = idx >> 7;
    const int n = idx & 127;
    g_powA[idx] = expf(logA[n] * (float)(j + 1));
}

// ---------------------------------------------------------------------------
// Local scan per (b, chunk): overwrite g_xproj with local h (h0 = 0),
// emit carry, stash raw last-row u.  (tf32 rounding happens in GEMM2's load.)
// ---------------------------------------------------------------------------
__global__ __launch_bounds__(128) void k_scan(const float* __restrict__ logA)
{
    const int b = blockIdx.x >> 6;
    const int c = blockIdx.x & 63;
    const int n = threadIdx.x;
    const float a = expf(logA[n]);

    float* p = g_xproj + ((size_t)(b * L_ + c * LC)) * N_ + n;
    float h = 0.0f, ulast = 0.0f;
    #pragma unroll 1
    for (int j = 0; j < LC; j += 8) {
        float u0 = p[0*N_], u1 = p[1*N_], u2 = p[2*N_], u3 = p[3*N_];
        float u4 = p[4*N_], u5 = p[5*N_], u6 = p[6*N_], u7 = p[7*N_];
        h = fmaf(a, h, u0); p[0*N_] = h;
        h = fmaf(a, h, u1); p[1*N_] = h;
        h = fmaf(a, h, u2); p[2*N_] = h;
        h = fmaf(a, h, u3); p[3*N_] = h;
        h = fmaf(a, h, u4); p[4*N_] = h;
        h = fmaf(a, h, u5); p[5*N_] = h;
        h = fmaf(a, h, u6); p[6*N_] = h;
        h = fmaf(a, h, u7); p[7*N_] = h;
        ulast = u7;
        p += 8*N_;
    }
    g_carry[(size_t)(b * NC + c) * N_ + n] = h;
    if (c == NC - 1)
        g_lastu[b * N_ + n] = ulast;
}

// ---------------------------------------------------------------------------
// Carry exclusive scan: 8 parallel blocks (one per b), batched register
// loads (64-deep MLP) then a register FMA chain.  Block 0 emits final_state.
// ---------------------------------------------------------------------------
__global__ __launch_bounds__(128) void k_carry(const float* __restrict__ logA,
                                               float* __restrict__ fs)
{
    const int b = blockIdx.x;
    const int n = threadIdx.x;
    const float aLc = expf((float)LC * logA[n]);

    float v[NC];
    #pragma unroll
    for (int c = 0; c < NC; c++)
        v[c] = g_carry[(size_t)(b * NC + c) * N_ + n];

    float H = 0.0f;
    #pragma unroll
    for (int c = 0; c < NC; c++) {
        g_Hprev[(size_t)(b * NC + c) * N_ + n] = H;
        H = fmaf(aLc, H, v[c]);
    }

    if (b == 0) {
        float s = 0.0f;
        #pragma unroll
        for (int bb = 0; bb < B_; bb++) s += g_lastu[bb * N_ + n];
        s *= (1.0f / B_);
        #pragma unroll
        for (int bb = 0; bb < B_; bb++) fs[bb * N_ + n] = s;
    }
}

// ---------------------------------------------------------------------------
extern "C" void kernel_launch(void* const* d_in, const int* in_sizes, int n_in,
                              void* d_out, int out_size)
{
    (void)in_sizes; (void)n_in; (void)out_size;
    const float* x    = (const float*)d_in[0];
    const float* Bw   = (const float*)d_in[1];
    const float* Cw   = (const float*)d_in[2];
    const float* logA = (const float*)d_in[3];
    const float* Dp   = (const float*)d_in[4];
    float* out = (float*)d_out;
    float* y_out  = out;                        // (B, L, D)
    float* fs_out = out + (size_t)M_ * D_;      // (B, N)

    float* g_xproj_p; cudaGetSymbolAddress((void**)&g_xproj_p, g_xproj);
    float* g_BwR_p;   cudaGetSymbolAddress((void**)&g_BwR_p,   g_BwR);
    float* g_CwR_p;   cudaGetSymbolAddress((void**)&g_CwR_p,   g_CwR);

    k_prep<<<512, 256>>>(Bw, Cw);
    k_pow <<<(LC*N_)/1024, 1024>>>(logA);

    // GEMM1: x (M x 1024) @ BwR^T -> g_xproj (M x 128)
    k_gemm<D_, false><<<M_/128, 256>>>(x, D_, g_BwR_p, D_, nullptr, nullptr, g_xproj_p);

    k_scan <<<B_*NC, 128>>>(logA);
    k_carry<<<B_, 128>>>(logA, fs_out);

    // GEMM2: h_true (M x 128, reconstructed in-load) @ CwR^T -> y + x*Dp
    dim3 g2(D_/128, M_/128);
    k_gemm<N_, true><<<g2, 256>>>(g_xproj_p, N_, g_CwR_p, N_, x, Dp, y_out);
}

// round 13
// speedup vs baseline: 2.5349x; 1.1912x over previous
#include <cuda_runtime.h>
#include <cstdint>

// Problem dims
#define B_  8
#define L_  4096
#define D_  1024
#define N_  128
#define M_  (B_*L_)      // 32768 rows
#define LC  64           // scan chunk length
#define NC  (L_/LC)      // 64 chunks

// Scratch (static device globals — no runtime allocation)
__device__ float g_xproj[(size_t)M_ * N_];   // 16 MB: x_proj -> h_true (tf32-rounded)
__device__ float g_carry[B_ * NC * N_];
__device__ float g_Hprev[B_ * NC * N_];
__device__ float g_lastu[B_ * N_];
__device__ float g_powA[LC * N_];            // A[n]^(j+1)
__device__ float g_BwR[N_ * D_];             // RN-tf32-rounded B_w
__device__ float g_CwR[D_ * N_];             // RN-tf32-rounded C_w

__device__ __forceinline__ float to_tf32(float f) {
    float r; asm("cvt.rna.tf32.f32 %0, %1;" : "=f"(r) : "f"(f)); return r;
}
__device__ __forceinline__ uint32_t smem_u32(const void* p) {
    uint32_t a;
    asm("{ .reg .u64 t; cvta.to.shared.u64 t, %1; cvt.u32.u64 %0, t; }" : "=r"(a) : "l"(p));
    return a;
}
__device__ __forceinline__ void cp16(uint32_t dst, const void* src) {
    asm volatile("cp.async.cg.shared.global [%0], [%1], 16;" :: "r"(dst), "l"(src) : "memory");
}
#define CP_COMMIT() asm volatile("cp.async.commit_group;" ::: "memory")
#define CP_WAIT(n)  asm volatile("cp.async.wait_group %0;" :: "n"(n) : "memory")

// ---------------------------------------------------------------------------
// mma.sync tf32 GEMM with 4-stage cp.async pipeline.
//   out[m, n] = sum_k A[m, k] * Brows[n, k]
//   Block tile 128(M) x 128(N), BK = 16 per stage, STAGES = 4.
//   8 warps in 2x4: warp tile 64(M) x 32(N), m16n8k8 fragments, 4x4 accums.
//   Smem row stride 20 floats (80 B, 16B-aligned): bank = (20r + c) mod 32
//   is a bijection over the fragment pattern -> conflict-free LDS; cp.async
//   16B chunks land at 16B-aligned offsets.
//   T = number of 16-wide K blocks.  RESID: epilogue adds x * Dp into y.
// ---------------------------------------------------------------------------
#define STAGES 4
#define STG_FLOATS 5120              // per stage: A 128*20 + B 128*20
#define SM_BYTES (STAGES * STG_FLOATS * 4)   // 81920

template<int T, bool RESID>
__global__ __launch_bounds__(256, 2) void k_gemm(
    const float* __restrict__ Aptr, int ldA,
    const float* __restrict__ Bptr, int ldB,
    const float* __restrict__ xres,
    const float* __restrict__ Dp,
    float* __restrict__ outp)
{
    extern __shared__ float smem[];
    const uint32_t sb = smem_u32(smem);
    const int tid  = threadIdx.x;
    const int warp = tid >> 5;
    const int lane = tid & 31;
    const int wm   = warp >> 2;        // 0..1 -> m offset wm*64
    const int wn   = warp & 3;         // 0..3 -> n offset wn*32
    const int grp  = lane >> 2;        // 0..7
    const int thr  = lane & 3;         // 0..3
    const int d0   = RESID ? blockIdx.x * 128 : 0;
    const int m0   = RESID ? blockIdx.y * 128 : blockIdx.x * 128;

    float d[4][4][4];
    #pragma unroll
    for (int mf = 0; mf < 4; mf++)
        #pragma unroll
        for (int nf = 0; nf < 4; nf++)
            #pragma unroll
            for (int q = 0; q < 4; q++) d[mf][nf][q] = 0.0f;

    // Loader map: row = tid>>1, two 16B chunks at float-cols (tid&1)*8, +4
    const int ar = tid >> 1;
    const int ac = (tid & 1) * 8;
    const int br = tid & 127;
    const int bc = (tid >> 7) * 8;

    const float* Ag = Aptr + (size_t)(m0 + ar) * ldA + ac;
    const float* Bg = Bptr + (size_t)(d0 + br) * ldB + bc;
    const uint32_t aDst = sb + (ar * 20 + ac) * 4;                  // within stage
    const uint32_t bDst = sb + (2560 + br * 20 + bc) * 4;

    auto load_tile = [&](int i, int s) {
        const uint32_t so = s * (STG_FLOATS * 4);
        const float* ag = Ag + (size_t)i * 16;
        const float* bg = Bg + (size_t)i * 16;
        cp16(aDst + so,      ag);
        cp16(aDst + so + 16, ag + 4);
        cp16(bDst + so,      bg);
        cp16(bDst + so + 16, bg + 4);
    };

    // Prologue: stages 0..STAGES-2
    #pragma unroll
    for (int i = 0; i < STAGES - 1; i++) {
        if (i < T) load_tile(i, i);
        CP_COMMIT();
    }

    for (int i = 0; i < T; i++) {
        CP_WAIT(STAGES - 2);            // tile i resident
        __syncthreads();                // all threads done computing tile i-1

        const int j = i + STAGES - 1;
        if (j < T) load_tile(j, j & (STAGES - 1));
        CP_COMMIT();

        const float* As = smem + (i & (STAGES - 1)) * STG_FLOATS;
        const float* Bs = As + 2560;

        #pragma unroll
        for (int ks = 0; ks < 2; ks++) {
            uint32_t a[4][4], b[4][2];
            #pragma unroll
            for (int mf = 0; mf < 4; mf++) {
                const float* ap = As + (wm*64 + mf*16) * 20 + ks*8;
                a[mf][0] = __float_as_uint(ap[ grp      * 20 + thr    ]);
                a[mf][1] = __float_as_uint(ap[(grp + 8) * 20 + thr    ]);
                a[mf][2] = __float_as_uint(ap[ grp      * 20 + thr + 4]);
                a[mf][3] = __float_as_uint(ap[(grp + 8) * 20 + thr + 4]);
            }
            #pragma unroll
            for (int nf = 0; nf < 4; nf++) {
                const float* bp = Bs + (wn*32 + nf*8) * 20 + ks*8;
                b[nf][0] = __float_as_uint(bp[grp * 20 + thr    ]);
                b[nf][1] = __float_as_uint(bp[grp * 20 + thr + 4]);
            }
            #pragma unroll
            for (int mf = 0; mf < 4; mf++)
                #pragma unroll
                for (int nf = 0; nf < 4; nf++)
                    asm volatile(
                        "mma.sync.aligned.m16n8k8.row.col.f32.tf32.tf32.f32 "
                        "{%0,%1,%2,%3}, {%4,%5,%6,%7}, {%8,%9}, {%0,%1,%2,%3};"
                        : "+f"(d[mf][nf][0]), "+f"(d[mf][nf][1]),
                          "+f"(d[mf][nf][2]), "+f"(d[mf][nf][3])
                        : "r"(a[mf][0]), "r"(a[mf][1]), "r"(a[mf][2]), "r"(a[mf][3]),
                          "r"(b[nf][0]), "r"(b[nf][1]));
        }
    }

    // Epilogue: c0/c1 at (row, 2*thr), c2/c3 at row+8.
    #pragma unroll
    for (int mf = 0; mf < 4; mf++) {
        const int mg = m0 + wm*64 + mf*16 + grp;
        #pragma unroll
        for (int nf = 0; nf < 4; nf++) {
            const int cg = wn*32 + nf*8 + 2*thr;
            if (!RESID) {
                *reinterpret_cast<float2*>(outp + (size_t)mg * N_ + cg) =
                    make_float2(d[mf][nf][0], d[mf][nf][1]);
                *reinterpret_cast<float2*>(outp + (size_t)(mg + 8) * N_ + cg) =
                    make_float2(d[mf][nf][2], d[mf][nf][3]);
            } else {
                const int dg = d0 + cg;
                float2 dv  = *reinterpret_cast<const float2*>(Dp + dg);
                float2 xv0 = *reinterpret_cast<const float2*>(xres + (size_t)mg * D_ + dg);
                float2 xv1 = *reinterpret_cast<const float2*>(xres + (size_t)(mg + 8) * D_ + dg);
                *reinterpret_cast<float2*>(outp + (size_t)mg * D_ + dg) =
                    make_float2(fmaf(xv0.x, dv.x, d[mf][nf][0]),
                                fmaf(xv0.y, dv.y, d[mf][nf][1]));
                *reinterpret_cast<float2*>(outp + (size_t)(mg + 8) * D_ + dg) =
                    make_float2(fmaf(xv1.x, dv.x, d[mf][nf][2]),
                                fmaf(xv1.y, dv.y, d[mf][nf][3]));
            }
        }
    }
}

// ---------------------------------------------------------------------------
// Prep: RN-round weights to tf32
// ---------------------------------------------------------------------------
__global__ __launch_bounds__(256) void k_prep(const float* __restrict__ Bw,
                                              const float* __restrict__ Cw)
{
    const int i = blockIdx.x * 256 + threadIdx.x;   // 131072 each
    g_BwR[i] = to_tf32(Bw[i]);
    g_CwR[i] = to_tf32(Cw[i]);
}

// powA table: g_powA[j][n] = A[n]^(j+1)
__global__ __launch_bounds__(1024) void k_pow(const float* __restrict__ logA)
{
    const int idx = blockIdx.x * 1024 + threadIdx.x;   // LC*N_ = 8192
    const int j = idx >> 7;
    const int n = idx & 127;
    g_powA[idx] = expf(logA[n] * (float)(j + 1));
}

// ---------------------------------------------------------------------------
// Local scan per (b, chunk): overwrite g_xproj with local h (h0 = 0),
// emit carry, stash raw last-row u.
// ---------------------------------------------------------------------------
__global__ __launch_bounds__(128) void k_scan(const float* __restrict__ logA)
{
    const int b = blockIdx.x >> 6;
    const int c = blockIdx.x & 63;
    const int n = threadIdx.x;
    const float a = expf(logA[n]);

    float* p = g_xproj + ((size_t)(b * L_ + c * LC)) * N_ + n;
    float h = 0.0f, ulast = 0.0f;
    #pragma unroll 1
    for (int j = 0; j < LC; j += 8) {
        float u0 = p[0*N_], u1 = p[1*N_], u2 = p[2*N_], u3 = p[3*N_];
        float u4 = p[4*N_], u5 = p[5*N_], u6 = p[6*N_], u7 = p[7*N_];
        h = fmaf(a, h, u0); p[0*N_] = h;
        h = fmaf(a, h, u1); p[1*N_] = h;
        h = fmaf(a, h, u2); p[2*N_] = h;
        h = fmaf(a, h, u3); p[3*N_] = h;
        h = fmaf(a, h, u4); p[4*N_] = h;
        h = fmaf(a, h, u5); p[5*N_] = h;
        h = fmaf(a, h, u6); p[6*N_] = h;
        h = fmaf(a, h, u7); p[7*N_] = h;
        ulast = u7;
        p += 8*N_;
    }
    g_carry[(size_t)(b * NC + c) * N_ + n] = h;
    if (c == NC - 1)
        g_lastu[b * N_ + n] = ulast;
}

// ---------------------------------------------------------------------------
// Carry exclusive scan: 8 parallel blocks, batched register loads then a
// register FMA chain.  Block 0 emits final_state.
// ---------------------------------------------------------------------------
__global__ __launch_bounds__(128) void k_carry(const float* __restrict__ logA,
                                               float* __restrict__ fs)
{
    const int b = blockIdx.x;
    const int n = threadIdx.x;
    const float aLc = expf((float)LC * logA[n]);

    float v[NC];
    #pragma unroll
    for (int c = 0; c < NC; c++)
        v[c] = g_carry[(size_t)(b * NC + c) * N_ + n];

    float H = 0.0f;
    #pragma unroll
    for (int c = 0; c < NC; c++) {
        g_Hprev[(size_t)(b * NC + c) * N_ + n] = H;
        H = fmaf(aLc, H, v[c]);
    }

    if (b == 0) {
        float s = 0.0f;
        #pragma unroll
        for (int bb = 0; bb < B_; bb++) s += g_lastu[bb * N_ + n];
        s *= (1.0f / B_);
        #pragma unroll
        for (int bb = 0; bb < B_; bb++) fs[bb * N_ + n] = s;
    }
}

// ---------------------------------------------------------------------------
// Fixup (element-parallel, all chunks): h_true = rn_tf32(local_h + A^(j+1)*Hp)
// ---------------------------------------------------------------------------
__global__ __launch_bounds__(256) void k_fix()
{
    const int b = blockIdx.x >> 6;
    const int c = blockIdx.x & 63;
    const int t = threadIdx.x;
    const int n  = t & 127;
    const int j0 = t >> 7;          // 0 or 1

    const float Hp = g_Hprev[(size_t)(b * NC + c) * N_ + n];
    float* p = g_xproj + ((size_t)(b * L_ + c * LC)) * N_;

    #pragma unroll
    for (int q = 0; q < 32; q++) {
        const int j = j0 + q * 2;
        const float pw = g_powA[j * N_ + n];
        p[j * N_ + n] = to_tf32(fmaf(pw, Hp, p[j * N_ + n]));
    }
}

// ---------------------------------------------------------------------------
extern "C" void kernel_launch(void* const* d_in, const int* in_sizes, int n_in,
                              void* d_out, int out_size)
{
    (void)in_sizes; (void)n_in; (void)out_size;
    const float* x    = (const float*)d_in[0];
    const float* Bw   = (const float*)d_in[1];
    const float* Cw   = (const float*)d_in[2];
    const float* logA = (const float*)d_in[3];
    const float* Dp   = (const float*)d_in[4];
    float* out = (float*)d_out;
    float* y_out  = out;                        // (B, L, D)
    float* fs_out = out + (size_t)M_ * D_;      // (B, N)

    float* g_xproj_p; cudaGetSymbolAddress((void**)&g_xproj_p, g_xproj);
    float* g_BwR_p;   cudaGetSymbolAddress((void**)&g_BwR_p,   g_BwR);
    float* g_CwR_p;   cudaGetSymbolAddress((void**)&g_CwR_p,   g_CwR);

    cudaFuncSetAttribute(k_gemm<64, false>,
                         cudaFuncAttributeMaxDynamicSharedMemorySize, SM_BYTES);
    cudaFuncSetAttribute(k_gemm<8, true>,
                         cudaFuncAttributeMaxDynamicSharedMemorySize, SM_BYTES);

    k_prep<<<512, 256>>>(Bw, Cw);
    k_pow <<<(LC*N_)/1024, 1024>>>(logA);

    // GEMM1: x (M x 1024) @ BwR^T -> g_xproj (M x 128)
    k_gemm<64, false><<<M_/128, 256, SM_BYTES>>>(
        x, D_, g_BwR_p, D_, nullptr, nullptr, g_xproj_p);

    k_scan <<<B_*NC, 128>>>(logA);
    k_carry<<<B_, 128>>>(logA, fs_out);
    k_fix  <<<B_*NC, 256>>>();

    // GEMM2: h_true (M x 128) @ CwR^T -> y + x*Dp
    dim3 g2(D_/128, M_/128);
    k_gemm<8, true><<<g2, 256, SM_BYTES>>>(
        g_xproj_p, N_, g_CwR_p, N_, x, Dp, y_out);
}